// round 1
// baseline (speedup 1.0000x reference)
#include <cuda_runtime.h>
#include <cstdint>

#define BB      32
#define PP      10208
#define CC      81
#define FG      80
#define PRE_K   400
#define MAXDET  100
#define SELCAP  2048
#define COLLCAP 2048
#define NBINS   4096
#define CONF    0.01f
#define NMST    0.45f
#define Wf      1280.0f
#define Hf      1024.0f
#define OFFC    1281.0f   // float(max(H,W)+1)

// ---------------- scratch (static device globals; allowed) ----------------
__device__ float        g_pmax[BB * PP];            // per-prior max fg score
__device__ int          g_selcnt[BB];
__device__ int          g_selidx[BB * SELCAP];
__device__ float        g_cscore[BB * SELCAP * FG]; // candidate scores
__device__ unsigned     g_hist[BB * NBINS];
__device__ float        g_topv[BB * PRE_K];
__device__ int          g_topi[BB * PRE_K];

// ---------------- K1: softmax denom + per-prior max fg score ----------------
__global__ void k1_priormax(const float* __restrict__ logits) {
    int gw   = (blockIdx.x * blockDim.x + threadIdx.x) >> 5;  // one warp per (b,p)
    int lane = threadIdx.x & 31;
    if (gw >= BB * PP) return;
    const float* row = logits + (size_t)gw * CC;
    float x0 = row[lane];
    float x1 = row[32 + lane];
    float x2 = (lane < CC - 64) ? row[64 + lane] : -1e30f;
    float m  = fmaxf(fmaxf(x0, x1), x2);                       // max over all 81
    float mf = fmaxf((lane == 0) ? -1e30f : x0, fmaxf(x1, x2));// max over classes 1..80
#pragma unroll
    for (int o = 16; o; o >>= 1) {
        m  = fmaxf(m,  __shfl_xor_sync(0xffffffffu, m,  o));
        mf = fmaxf(mf, __shfl_xor_sync(0xffffffffu, mf, o));
    }
    float s = expf(x0 - m) + expf(x1 - m) + ((lane < CC - 64) ? expf(x2 - m) : 0.0f);
#pragma unroll
    for (int o = 16; o; o >>= 1) s += __shfl_xor_sync(0xffffffffu, s, o);
    if (lane == 0) g_pmax[gw] = expf(mf - m) / s;
}

// ------------- boundary-bin finder (block of 1024 threads required) ---------
// returns largest bin Bb such that count(entries in bins >= Bb) >= T
__device__ __forceinline__ int find_boundary(const unsigned* h, int T) {
    __shared__ unsigned ps[1024];
    __shared__ int minR;
    int t = threadIdx.x;
    if (t == 0) minR = 0x7fffffff;
    int base = 4095 - 4 * t;  // reversed chunk of 4 bins
    unsigned part = h[base] + h[base - 1] + h[base - 2] + h[base - 3];
    ps[t] = part;
    __syncthreads();
    for (int d = 1; d < 1024; d <<= 1) {
        unsigned v = (t >= d) ? ps[t - d] : 0u;
        __syncthreads();
        ps[t] += v;
        __syncthreads();
    }
    unsigned cum = ps[t] - part;  // exclusive prefix (from top)
#pragma unroll
    for (int i2 = 0; i2 < 4; i2++) {
        cum += h[4095 - (4 * t + i2)];
        if (cum >= (unsigned)T) { atomicMin(&minR, 4 * t + i2); break; }
    }
    __syncthreads();
    int r = minR;
    return (r == 0x7fffffff) ? 0 : (4095 - r);
}

// ---------------- K2: per batch, select covering prior set ----------------
__global__ void __launch_bounds__(1024) k2_selpriors() {
    int b = blockIdx.x, t = threadIdx.x;
    __shared__ unsigned h[NBINS];
    if (t == 0) g_selcnt[b] = 0;
    for (int i = t; i < NBINS; i += 1024) { h[i] = 0u; g_hist[b * NBINS + i] = 0u; }
    __syncthreads();
    for (int i = t; i < PP; i += 1024) {
        unsigned bits = __float_as_uint(g_pmax[b * PP + i]);
        atomicAdd(&h[bits >> 18], 1u);
    }
    __syncthreads();
    int Bb = find_boundary(h, 512);
    for (int i = t; i < PP; i += 1024) {
        unsigned bits = __float_as_uint(g_pmax[b * PP + i]);
        if ((int)(bits >> 18) >= Bb) {
            int p = atomicAdd(&g_selcnt[b], 1);
            if (p < SELCAP) g_selidx[b * SELCAP + p] = i;
        }
    }
}

// --------- K3a: recompute softmax scores for selected priors + histogram ----
__global__ void k3a_scores(const float* __restrict__ logits) {
    int b    = blockIdx.y;
    int slot = blockIdx.x * (blockDim.x >> 5) + (threadIdx.x >> 5);
    int lane = threadIdx.x & 31;
    int ns   = min(g_selcnt[b], SELCAP);
    if (slot >= ns) return;
    int prior = g_selidx[b * SELCAP + slot];
    const float* row = logits + ((size_t)b * PP + prior) * CC;
    float x0 = row[lane];
    float x1 = row[32 + lane];
    float x2 = (lane < CC - 64) ? row[64 + lane] : -1e30f;
    float m = fmaxf(fmaxf(x0, x1), x2);
#pragma unroll
    for (int o = 16; o; o >>= 1) m = fmaxf(m, __shfl_xor_sync(0xffffffffu, m, o));
    float s = expf(x0 - m) + expf(x1 - m) + ((lane < CC - 64) ? expf(x2 - m) : 0.0f);
#pragma unroll
    for (int o = 16; o; o >>= 1) s += __shfl_xor_sync(0xffffffffu, s, o);

    unsigned* hb = &g_hist[b * NBINS];
    float* outp  = &g_cscore[((size_t)b * SELCAP + slot) * FG];
    if (lane > 0) {                         // class = lane  -> fg idx lane-1
        float sc = expf(x0 - m) / s;
        outp[lane - 1] = sc;
        atomicAdd(&hb[__float_as_uint(sc) >> 18], 1u);
    }
    {                                       // class = 32+lane -> fg idx 31+lane
        float sc = expf(x1 - m) / s;
        outp[31 + lane] = sc;
        atomicAdd(&hb[__float_as_uint(sc) >> 18], 1u);
    }
    if (lane < CC - 64) {                   // class = 64+lane -> fg idx 63+lane
        float sc = expf(x2 - m) / s;
        outp[63 + lane] = sc;
        atomicAdd(&hb[__float_as_uint(sc) >> 18], 1u);
    }
}

// --------- K3b: exact top-400 (value desc, flat index asc) per batch -------
__global__ void __launch_bounds__(1024) k3b_topk() {
    int b = blockIdx.x, t = threadIdx.x;
    __shared__ unsigned h[NBINS];
    __shared__ unsigned long long keys[COLLCAP];
    __shared__ int cnt;
    if (t == 0) cnt = 0;
    for (int i = t; i < NBINS; i += 1024) h[i] = g_hist[b * NBINS + i];
    for (int i = t; i < COLLCAP; i += 1024) keys[i] = 0xFFFFFFFFFFFFFFFFull;
    __syncthreads();
    int Bb = find_boundary(h, PRE_K);
    int ns = min(g_selcnt[b], SELCAP);
    int n  = ns * FG;
    for (int i = t; i < n; i += 1024) {
        unsigned bits = __float_as_uint(g_cscore[(size_t)b * SELCAP * FG + i]);
        if ((int)(bits >> 18) >= Bb) {
            int p = atomicAdd(&cnt, 1);
            if (p < COLLCAP) {
                int slot = i / FG, c = i - slot * FG;
                unsigned fidx = (unsigned)g_selidx[b * SELCAP + slot] * FG + (unsigned)c;
                keys[p] = ((unsigned long long)(~bits) << 32) | (unsigned long long)fidx;
            }
        }
    }
    __syncthreads();
    // bitonic sort 2048 keys ascending (smallest key = highest score, lowest idx)
    for (int k = 2; k <= COLLCAP; k <<= 1) {
        for (int j = k >> 1; j > 0; j >>= 1) {
#pragma unroll
            for (int e = 0; e < 2; e++) {
                int i = t + e * 1024;
                int ixj = i ^ j;
                if (ixj > i) {
                    unsigned long long a = keys[i], bq = keys[ixj];
                    bool sw = ((i & k) == 0) ? (a > bq) : (a < bq);
                    if (sw) { keys[i] = bq; keys[ixj] = a; }
                }
            }
            __syncthreads();
        }
    }
    if (t < PRE_K) {
        unsigned long long key = keys[t];
        unsigned bits = ~(unsigned)(key >> 32);
        g_topv[b * PRE_K + t] = __uint_as_float(bits);
        g_topi[b * PRE_K + t] = (int)(key & 0xFFFFFFFFull);
    }
}

// --------------- K4: decode + bitmask NMS + final top-100 ------------------
__global__ void __launch_bounds__(1024) k4_nms(const float* __restrict__ bbox,
                                               const float* __restrict__ priors,
                                               float* __restrict__ out) {
    int b = blockIdx.x, t = threadIdx.x, lane = t & 31, w = t >> 5;
    __shared__ float ox1[PRE_K], oy1[PRE_K], ox2[PRE_K], oy2[PRE_K], ar[PRE_K];
    __shared__ float bx1[PRE_K], by1[PRE_K], bx2[PRE_K], by2[PRE_K], tv[PRE_K];
    __shared__ int   cl[PRE_K];
    __shared__ unsigned mask[PRE_K * 13];
    __shared__ unsigned initm[13], finm[13];
    __shared__ int fi[MAXDET];
    __shared__ int warpcnt[32], warpoff[33];

    for (int i = t; i < PRE_K * 13; i += 1024) mask[i] = 0u;
    if (t < PRE_K) {
        float v = g_topv[b * PRE_K + t];
        int fidx = g_topi[b * PRE_K + t];
        if (fidx < 0 || fidx >= PP * FG) { fidx = 0; v = 0.0f; }  // safety vs padding
        int prior = fidx / FG;
        int c = fidx - prior * FG + 1;
        tv[t] = v; cl[t] = c;
        const float* L  = bbox   + ((size_t)b * PP + prior) * 4;
        const float* Pr = priors + (size_t)prior * 4;
        float px = Pr[0], py = Pr[1], pw = Pr[2], ph = Pr[3];
        float cx = L[0] * 0.1f * pw + px;
        float cy = L[1] * 0.1f * ph + py;
        float sw = expf(L[2] * 0.2f) * pw;
        float sh = expf(L[3] * 0.2f) * ph;
        float X1 = (cx - sw * 0.5f) * Wf, Y1 = (cy - sh * 0.5f) * Hf;
        float X2 = (cx + sw * 0.5f) * Wf, Y2 = (cy + sh * 0.5f) * Hf;
        bx1[t] = X1; by1[t] = Y1; bx2[t] = X2; by2[t] = Y2;
        float off = (float)c * OFFC;
        float a1 = X1 + off, a2 = Y1 + off, a3 = X2 + off, a4 = Y2 + off;
        ox1[t] = a1; oy1[t] = a2; ox2[t] = a3; oy2[t] = a4;
        ar[t] = (a3 - a1) * (a4 - a2);   // area on OFFSET coords, like the reference
    }
    __syncthreads();
    // initial removed mask = !(topv > CONF)
    if (w < 13) {
        bool rm = true;
        if (t < PRE_K) rm = !(tv[t] > CONF);
        unsigned ball = __ballot_sync(0xffffffffu, rm);
        if (lane == 0) initm[w] = ball;
    }
    __syncthreads();
    // pairwise suppression bitmasks
    for (int idx = t; idx < PRE_K * PRE_K; idx += 1024) {
        int i = idx / PRE_K, j = idx - i * PRE_K;
        if (j > i) {
            float ltx = fmaxf(ox1[i], ox1[j]);
            float lty = fmaxf(oy1[i], oy1[j]);
            float rbx = fminf(ox2[i], ox2[j]);
            float rby = fminf(oy2[i], oy2[j]);
            float wv = fmaxf(rbx - ltx, 0.0f), hv = fmaxf(rby - lty, 0.0f);
            float inter = wv * hv;
            float iou = inter / (ar[i] + ar[j] - inter + 1e-9f);
            if (iou > NMST) atomicOr(&mask[i * 13 + (j >> 5)], 1u << (j & 31));
        }
    }
    __syncthreads();
    // serial greedy walk (warp 0), exactly the reference scan semantics
    if (w == 0) {
        unsigned remv = (lane < 13) ? initm[lane] : 0u;
        for (int i = 0; i < PRE_K; i++) {
            unsigned word = __shfl_sync(0xffffffffu, remv, i >> 5);
            if (!(word & (1u << (i & 31)))) {
                if (lane < 13) remv |= mask[i * 13 + lane];
            }
        }
        if (lane < 13) finm[lane] = remv;
    }
    __syncthreads();
    // keep flags + stable compaction rank (kept in order, then non-kept)
    bool kp = false;
    if (t < PRE_K) kp = !((finm[t >> 5] >> (t & 31)) & 1u);
    unsigned ball = __ballot_sync(0xffffffffu, kp);
    if (lane == 0) warpcnt[w] = __popc(ball);
    __syncthreads();
    if (t == 0) {
        int acc = 0;
        for (int i = 0; i < 32; i++) { warpoff[i] = acc; acc += warpcnt[i]; }
        warpoff[32] = acc;
    }
    __syncthreads();
    int nk = warpoff[32];
    if (t < PRE_K) {
        int rk = warpoff[w] + __popc(ball & ((1u << lane) - 1u));
        int pos = kp ? rk : nk + (t - rk);
        if (pos < MAXDET) fi[pos] = t;
    }
    __syncthreads();
    if (t < MAXDET) {
        int j = fi[t];
        bool kj = !((finm[j >> 5] >> (j & 31)) & 1u);
        int base = (b * MAXDET + t) * 4;
        out[base + 0] = bx1[j];
        out[base + 1] = by1[j];
        out[base + 2] = bx2[j];
        out[base + 3] = by2[j];
        out[BB * MAXDET * 4 + b * MAXDET + t] = (float)cl[j];
        out[BB * MAXDET * 5 + b * MAXDET + t] = kj ? tv[j] : 0.0f;
    }
}

// ------------------------------ launcher -----------------------------------
extern "C" void kernel_launch(void* const* d_in, const int* in_sizes, int n_in,
                              void* d_out, int out_size) {
    const float* logits = (const float*)d_in[0];  // (32, P, 81)
    const float* bbox   = (const float*)d_in[1];  // (32, P, 4)
    const float* priors = (const float*)d_in[2];  // (P, 4)
    float* out = (float*)d_out;

    int totalThreads = BB * PP * 32;   // one warp per (b, prior)
    k1_priormax<<<(totalThreads + 255) / 256, 256>>>(logits);
    k2_selpriors<<<BB, 1024>>>();
    k3a_scores<<<dim3(SELCAP / 8, BB), 256>>>(logits);
    k3b_topk<<<BB, 1024>>>();
    k4_nms<<<BB, 1024>>>(bbox, priors, out);
}

// round 2
// speedup vs baseline: 1.2223x; 1.2223x over previous
#include <cuda_runtime.h>
#include <cstdint>

#define BB      32
#define PP      10208
#define CC      81
#define FG      80
#define PRE_K   400
#define MAXDET  100
#define SELCAP  2048
#define KEYCAP  2048
#define NBINS   4096
#define CONF    0.01f
#define NMST    0.45f
#define Wf      1280.0f
#define Hf      1024.0f
#define OFFC    1281.0f   // float(max(H,W)+1)

// ---------------- global scratch (static device globals; allowed) ----------
__device__ float g_pmax[BB * PP];                 // per-prior max fg score
__device__ float g_cscore[BB * SELCAP * FG];      // candidate fg scores

// ---------------- K1: softmax denom + per-prior max fg score ---------------
__global__ void k1_priormax(const float* __restrict__ logits) {
    int gw   = (blockIdx.x * blockDim.x + threadIdx.x) >> 5;  // warp per (b,p)
    int lane = threadIdx.x & 31;
    if (gw >= BB * PP) return;
    const float* row = logits + (size_t)gw * CC;
    float x0 = row[lane];
    float x1 = row[32 + lane];
    float x2 = (lane < CC - 64) ? row[64 + lane] : -1e30f;
    float m  = fmaxf(fmaxf(x0, x1), x2);                        // max all 81
    float mf = fmaxf((lane == 0) ? -1e30f : x0, fmaxf(x1, x2)); // max fg 1..80
#pragma unroll
    for (int o = 16; o; o >>= 1) {
        m  = fmaxf(m,  __shfl_xor_sync(0xffffffffu, m,  o));
        mf = fmaxf(mf, __shfl_xor_sync(0xffffffffu, mf, o));
    }
    float s = expf(x0 - m) + expf(x1 - m) + ((lane < CC - 64) ? expf(x2 - m) : 0.0f);
#pragma unroll
    for (int o = 16; o; o >>= 1) s += __shfl_xor_sync(0xffffffffu, s, o);
    if (lane == 0) g_pmax[gw] = expf(mf - m) / s;
}

// ---------------- shared-mem layout for the fused kernel -------------------
#define OFF_HIST   0
#define OFF_SELIDX 16384
#define OFF_KEYS   24576
#define OFF_F      40960
#define OFF_CL     56960
#define OFF_MASK   58560
#define DYN_BYTES  79360

// fast boundary finder: largest bin Bb with count(bins >= Bb) >= T.
// Also writes count of bins strictly above Bb to *s_above. Block = 1024 thr.
__device__ __forceinline__ int boundary(const unsigned* __restrict__ h, int T,
                                        int* s_minR, unsigned* s_above,
                                        unsigned* s_wsum) {
    int t = threadIdx.x, lane = t & 31, w = t >> 5;
    if (t == 0) { *s_minR = 0x7fffffff; *s_above = 0u; }
    __syncthreads();
    int base = 4095 - 4 * t;
    unsigned c0 = h[base], c1 = h[base - 1], c2 = h[base - 2], c3 = h[base - 3];
    unsigned part = c0 + c1 + c2 + c3;
    unsigned v = part;
#pragma unroll
    for (int o = 1; o < 32; o <<= 1) {
        unsigned u = __shfl_up_sync(0xffffffffu, v, o);
        if (lane >= o) v += u;
    }
    if (lane == 31) s_wsum[w] = v;
    __syncthreads();
    if (w == 0) {
        unsigned x = s_wsum[lane];
#pragma unroll
        for (int o = 1; o < 32; o <<= 1) {
            unsigned u = __shfl_up_sync(0xffffffffu, x, o);
            if (lane >= o) x += u;
        }
        s_wsum[lane] = x;
    }
    __syncthreads();
    unsigned excl = ((w > 0) ? s_wsum[w - 1] : 0u) + (v - part);
    unsigned cum = excl, myAbove = 0;
    int myR = 0x7fffffff;
    unsigned cs[4] = {c0, c1, c2, c3};
#pragma unroll
    for (int i2 = 0; i2 < 4; i2++) {
        unsigned prev = cum;
        cum += cs[i2];
        if (myR == 0x7fffffff && cum >= (unsigned)T) { myR = 4 * t + i2; myAbove = prev; }
    }
    if (myR != 0x7fffffff) atomicMin(s_minR, myR);
    __syncthreads();
    int r = *s_minR;
    if (r == myR && myR != 0x7fffffff) *s_above = myAbove;
    __syncthreads();
    return (r == 0x7fffffff) ? 0 : (4095 - r);
}

// bitonic sort n (pow2, multiple of 64) 64-bit keys ascending; block = 1024 thr
__device__ __forceinline__ void bitonic(unsigned long long* keys, int n) {
    int t = threadIdx.x;
    // k = 2..32 fully in registers (warp covers 32 consecutive elements)
    for (int base = t; base < n; base += 1024) {
        unsigned long long key = keys[base];
#pragma unroll
        for (int k2 = 2; k2 <= 32; k2 <<= 1) {
            bool up = ((base & k2) == 0);
#pragma unroll
            for (int j = k2 >> 1; j >= 1; j >>= 1) {
                unsigned long long other = __shfl_xor_sync(0xffffffffu, key, j);
                bool keepSmall = (((base & j) == 0) == up);
                bool take = keepSmall ? (other < key) : (other > key);
                if (take) key = other;
            }
        }
        keys[base] = key;
    }
    __syncthreads();
    for (int k = 64; k <= n; k <<= 1) {
        for (int j = k >> 1; j >= 32; j >>= 1) {
            for (int u = t; u < (n >> 1); u += 1024) {
                int i = ((u & ~(j - 1)) << 1) | (u & (j - 1));
                int p = i | j;
                unsigned long long a = keys[i], bk = keys[p];
                bool up = ((i & k) == 0);
                if ((a > bk) == up) { keys[i] = bk; keys[p] = a; }
            }
            __syncthreads();
        }
        for (int base = t; base < n; base += 1024) {
            unsigned long long key = keys[base];
            bool up = ((base & k) == 0);
#pragma unroll
            for (int j = 16; j >= 1; j >>= 1) {
                unsigned long long other = __shfl_xor_sync(0xffffffffu, key, j);
                bool keepSmall = (((base & j) == 0) == up);
                bool take = keepSmall ? (other < key) : (other > key);
                if (take) key = other;
            }
            keys[base] = key;
        }
        __syncthreads();
    }
}

// -------- fused: select priors -> scores -> exact top-400 -> NMS -> out ----
__global__ void __launch_bounds__(1024) k2_fused(const float* __restrict__ logits,
                                                 const float* __restrict__ bbox,
                                                 const float* __restrict__ priors,
                                                 float* __restrict__ out) {
    extern __shared__ unsigned char dyn[];
    unsigned*           hist   = (unsigned*)(dyn + OFF_HIST);
    int*                selidx = (int*)(dyn + OFF_SELIDX);
    unsigned long long* keys   = (unsigned long long*)(dyn + OFF_KEYS);
    float* F   = (float*)(dyn + OFF_F);
    float *ox1 = F, *oy1 = F + 400, *ox2 = F + 800, *oy2 = F + 1200, *ar = F + 1600;
    float *bx1 = F + 2000, *by1 = F + 2400, *bx2 = F + 2800, *by2 = F + 3200, *tv = F + 3600;
    int*       cl   = (int*)(dyn + OFF_CL);
    unsigned*  mask = (unsigned*)(dyn + OFF_MASK);

    __shared__ unsigned s_wsum[32];
    __shared__ int s_minR, s_cnt;
    __shared__ unsigned s_above;
    __shared__ unsigned initm[13], finm[13];
    __shared__ int fi[MAXDET], warpcnt[32], warpoff[33];

    int b = blockIdx.x, t = threadIdx.x, lane = t & 31, w = t >> 5;

    // ---------- phase A: select covering prior set (T = 512) ----------
    if (t == 0) s_cnt = 0;
    for (int i = t; i < NBINS; i += 1024) hist[i] = 0u;
    __syncthreads();
    for (int i = t; i < PP; i += 1024)
        atomicAdd(&hist[__float_as_uint(g_pmax[b * PP + i]) >> 18], 1u);
    __syncthreads();
    int BbA = boundary(hist, 512, &s_minR, &s_above, s_wsum);
    int needA = 512 - (int)s_above;
    for (int i = t; i < NBINS; i += 1024) hist[i] = 0u;
    __syncthreads();
    for (int i = t; i < PP; i += 1024) {
        unsigned bits = __float_as_uint(g_pmax[b * PP + i]);
        if ((int)(bits >> 18) == BbA) atomicAdd(&hist[(bits >> 6) & 0xFFF], 1u);
    }
    __syncthreads();
    int Bb2A = boundary(hist, needA, &s_minR, &s_above, s_wsum);
    for (int i = t; i < PP; i += 1024) {
        unsigned bits = __float_as_uint(g_pmax[b * PP + i]);
        int key = (int)(bits >> 18);
        bool sel = (key > BbA) || (key == BbA && (int)((bits >> 6) & 0xFFF) >= Bb2A);
        if (sel) {
            int p = atomicAdd(&s_cnt, 1);
            if (p < SELCAP) selidx[p] = i;
        }
    }
    __syncthreads();
    int ns = min(s_cnt, SELCAP);

    // ---------- phase B: recompute softmax for selected priors ----------
    for (int i = t; i < NBINS; i += 1024) hist[i] = 0u;
    __syncthreads();
    for (int slot = w; slot < ns; slot += 32) {
        int prior = selidx[slot];
        const float* row = logits + ((size_t)b * PP + prior) * CC;
        float x0 = row[lane];
        float x1 = row[32 + lane];
        float x2 = (lane < CC - 64) ? row[64 + lane] : -1e30f;
        float m = fmaxf(fmaxf(x0, x1), x2);
#pragma unroll
        for (int o = 16; o; o >>= 1) m = fmaxf(m, __shfl_xor_sync(0xffffffffu, m, o));
        float s = expf(x0 - m) + expf(x1 - m) + ((lane < CC - 64) ? expf(x2 - m) : 0.0f);
#pragma unroll
        for (int o = 16; o; o >>= 1) s += __shfl_xor_sync(0xffffffffu, s, o);
        float* outp = &g_cscore[((size_t)b * SELCAP + slot) * FG];
        if (lane > 0) {
            float sc = expf(x0 - m) / s;
            outp[lane - 1] = sc;
            atomicAdd(&hist[__float_as_uint(sc) >> 18], 1u);
        }
        {
            float sc = expf(x1 - m) / s;
            outp[31 + lane] = sc;
            atomicAdd(&hist[__float_as_uint(sc) >> 18], 1u);
        }
        if (lane < CC - 64) {
            float sc = expf(x2 - m) / s;
            outp[63 + lane] = sc;
            atomicAdd(&hist[__float_as_uint(sc) >> 18], 1u);
        }
    }
    __syncthreads();

    // ---------- phase C: two-level threshold for exact top-400 ----------
    int n80 = ns * FG;
    const float* cs = &g_cscore[(size_t)b * SELCAP * FG];
    int BbS = boundary(hist, PRE_K, &s_minR, &s_above, s_wsum);
    int needS = PRE_K - (int)s_above;
    for (int i = t; i < NBINS; i += 1024) hist[i] = 0u;
    __syncthreads();
    for (int i = t; i < n80; i += 1024) {
        unsigned bits = __float_as_uint(cs[i]);
        if ((int)(bits >> 18) == BbS) atomicAdd(&hist[(bits >> 6) & 0xFFF], 1u);
    }
    __syncthreads();
    int Bb2S = boundary(hist, needS, &s_minR, &s_above, s_wsum);

    // ---------- phase D: collect candidates + sort ----------
    if (t == 0) s_cnt = 0;
    for (int i = t; i < KEYCAP; i += 1024) keys[i] = 0xFFFFFFFFFFFFFFFFull;
    __syncthreads();
    for (int i = t; i < n80; i += 1024) {
        unsigned bits = __float_as_uint(cs[i]);
        int key = (int)(bits >> 18);
        bool sel = (key > BbS) || (key == BbS && (int)((bits >> 6) & 0xFFF) >= Bb2S);
        if (sel) {
            int p = atomicAdd(&s_cnt, 1);
            if (p < KEYCAP) {
                int slot = i / FG, c = i - slot * FG;
                unsigned fidx = (unsigned)selidx[slot] * FG + (unsigned)c;
                keys[p] = ((unsigned long long)(~bits) << 32) | (unsigned long long)fidx;
            }
        }
    }
    __syncthreads();
    int cnt = min(s_cnt, KEYCAP);
    int sortn = (cnt <= 512) ? 512 : (cnt <= 1024 ? 1024 : 2048);
    bitonic(keys, sortn);

    // ---------- phase E: decode + bitmask NMS + stable top-100 ----------
    for (int i = t; i < PRE_K * 13; i += 1024) mask[i] = 0u;
    if (t < PRE_K) {
        unsigned long long key = keys[t];
        unsigned bits = ~(unsigned)(key >> 32);
        float v = __uint_as_float(bits);
        int fidx = (int)(key & 0xFFFFFFFFull);
        if (fidx < 0 || fidx >= PP * FG) { fidx = 0; v = 0.0f; }
        int prior = fidx / FG;
        int c = fidx - prior * FG + 1;
        tv[t] = v; cl[t] = c;
        const float* L  = bbox   + ((size_t)b * PP + prior) * 4;
        const float* Pr = priors + (size_t)prior * 4;
        float px = Pr[0], py = Pr[1], pw = Pr[2], ph = Pr[3];
        float cx = L[0] * 0.1f * pw + px;
        float cy = L[1] * 0.1f * ph + py;
        float sw = expf(L[2] * 0.2f) * pw;
        float sh = expf(L[3] * 0.2f) * ph;
        float X1 = (cx - sw * 0.5f) * Wf, Y1 = (cy - sh * 0.5f) * Hf;
        float X2 = (cx + sw * 0.5f) * Wf, Y2 = (cy + sh * 0.5f) * Hf;
        bx1[t] = X1; by1[t] = Y1; bx2[t] = X2; by2[t] = Y2;
        float off = (float)c * OFFC;
        float a1 = X1 + off, a2 = Y1 + off, a3 = X2 + off, a4 = Y2 + off;
        ox1[t] = a1; oy1[t] = a2; ox2[t] = a3; oy2[t] = a4;
        ar[t] = (a3 - a1) * (a4 - a2);
    }
    __syncthreads();
    if (w < 13) {
        bool rm = true;
        if (t < PRE_K) rm = !(tv[t] > CONF);
        unsigned ball = __ballot_sync(0xffffffffu, rm);
        if (lane == 0) initm[w] = ball;
    }
    __syncthreads();
    for (int idx = t; idx < PRE_K * PRE_K; idx += 1024) {
        int i = idx / PRE_K, j = idx - i * PRE_K;
        if (j > i) {
            float ltx = fmaxf(ox1[i], ox1[j]);
            float lty = fmaxf(oy1[i], oy1[j]);
            float rbx = fminf(ox2[i], ox2[j]);
            float rby = fminf(oy2[i], oy2[j]);
            float wv = fmaxf(rbx - ltx, 0.0f), hv = fmaxf(rby - lty, 0.0f);
            float inter = wv * hv;
            float iou = inter / (ar[i] + ar[j] - inter + 1e-9f);
            if (iou > NMST) atomicOr(&mask[i * 13 + (j >> 5)], 1u << (j & 31));
        }
    }
    __syncthreads();
    if (w == 0) {  // serial greedy walk, next-row prefetch to shorten the chain
        unsigned remv = (lane < 13) ? initm[lane] : 0u;
        unsigned nextrow = (lane < 13) ? mask[lane] : 0u;
        for (int i = 0; i < PRE_K; i++) {
            unsigned row = nextrow;
            if (i + 1 < PRE_K) nextrow = (lane < 13) ? mask[(i + 1) * 13 + lane] : 0u;
            unsigned word = __shfl_sync(0xffffffffu, remv, i >> 5);
            if (!(word & (1u << (i & 31)))) remv |= row;
        }
        if (lane < 13) finm[lane] = remv;
    }
    __syncthreads();
    bool kp = false;
    if (t < PRE_K) kp = !((finm[t >> 5] >> (t & 31)) & 1u);
    unsigned ball = __ballot_sync(0xffffffffu, kp);
    if (lane == 0) warpcnt[w] = __popc(ball);
    __syncthreads();
    if (t == 0) {
        int acc = 0;
        for (int i = 0; i < 32; i++) { warpoff[i] = acc; acc += warpcnt[i]; }
        warpoff[32] = acc;
    }
    __syncthreads();
    int nk = warpoff[32];
    if (t < PRE_K) {
        int rk = warpoff[w] + __popc(ball & ((1u << lane) - 1u));
        int pos = kp ? rk : nk + (t - rk);
        if (pos < MAXDET) fi[pos] = t;
    }
    __syncthreads();
    if (t < MAXDET) {
        int j = fi[t];
        bool kj = !((finm[j >> 5] >> (j & 31)) & 1u);
        int base = (b * MAXDET + t) * 4;
        out[base + 0] = bx1[j];
        out[base + 1] = by1[j];
        out[base + 2] = bx2[j];
        out[base + 3] = by2[j];
        out[BB * MAXDET * 4 + b * MAXDET + t] = (float)cl[j];
        out[BB * MAXDET * 5 + b * MAXDET + t] = kj ? tv[j] : 0.0f;
    }
}

// ------------------------------ launcher -----------------------------------
extern "C" void kernel_launch(void* const* d_in, const int* in_sizes, int n_in,
                              void* d_out, int out_size) {
    const float* logits = (const float*)d_in[0];  // (32, P, 81)
    const float* bbox   = (const float*)d_in[1];  // (32, P, 4)
    const float* priors = (const float*)d_in[2];  // (P, 4)
    float* out = (float*)d_out;

    cudaFuncSetAttribute(k2_fused, cudaFuncAttributeMaxDynamicSharedMemorySize,
                         DYN_BYTES);

    int totalThreads = BB * PP * 32;  // one warp per (b, prior)
    k1_priormax<<<(totalThreads + 255) / 256, 256>>>(logits);
    k2_fused<<<BB, 1024, DYN_BYTES>>>(logits, bbox, priors, out);
}